// round 2
// baseline (speedup 1.0000x reference)
#include <cuda_runtime.h>
#include <math.h>

// Problem constants (fixed by the dataset problem)
#define BATCH        2048
#define IN_DIM       4096
#define OUT_DIM      1024
#define N_EDGES_MAX  16384
#define ROWS_PER_BLK 8
#define THREADS      1024   // == OUT_DIM, one node per thread

// CSR row offsets for the (sorted) edge_dst array. __device__ global scratch
// (no allocation allowed in kernel_launch).
__device__ int g_offs[OUT_DIM + 1];

// Prologue: offs[o] = lower_bound(edge_dst, o). edge_dst is sorted ascending.
__global__ void build_offsets_kernel(const int* __restrict__ edge_dst, int n_edges) {
    int o = blockIdx.x * blockDim.x + threadIdx.x;
    if (o > OUT_DIM) return;
    int lo = 0, hi = n_edges;
    while (lo < hi) {
        int mid = (lo + hi) >> 1;
        if (edge_dst[mid] < o) lo = mid + 1; else hi = mid;
    }
    g_offs[o] = lo;
}

// Main: each block stages ROWS_PER_BLK batch rows of x into shared memory
// (coalesced), each thread owns one output node and walks its CSR edge
// segment, accumulating ROWS_PER_BLK partial sums in registers.
extern __shared__ float xs[];  // [ROWS_PER_BLK][IN_DIM] = 128 KB

__global__ __launch_bounds__(THREADS, 1)
void sparse_node_main_kernel(const float* __restrict__ x,
                             const float* __restrict__ weights,
                             const int* __restrict__ edge_src,
                             float* __restrict__ out) {
    const int r0 = blockIdx.x * ROWS_PER_BLK;

    // ---- Stage 8 rows of x into smem, fully coalesced float4 ----
    {
        const float4* __restrict__ xg =
            reinterpret_cast<const float4*>(x + (size_t)r0 * IN_DIM);
        float4* xs4 = reinterpret_cast<float4*>(xs);
        const int n4 = ROWS_PER_BLK * IN_DIM / 4;  // 8192
        #pragma unroll
        for (int i = 0; i < n4 / THREADS; i++)
            xs4[i * THREADS + threadIdx.x] = xg[i * THREADS + threadIdx.x];
    }
    __syncthreads();

    // ---- Each thread owns output node o = threadIdx.x ----
    const int o   = threadIdx.x;
    const int beg = g_offs[o];
    const int end = g_offs[o + 1];

    float acc[ROWS_PER_BLK];
    #pragma unroll
    for (int r = 0; r < ROWS_PER_BLK; r++) acc[r] = 0.0f;

    for (int e = beg; e < end; e++) {
        const int   s = edge_src[e];
        const float w = weights[e];
        #pragma unroll
        for (int r = 0; r < ROWS_PER_BLK; r++)
            acc[r] = fmaf(xs[r * IN_DIM + s], w, acc[r]);
    }

    // ---- Fused tanh -> sigmoid epilogue, coalesced stores ----
    #pragma unroll
    for (int r = 0; r < ROWS_PER_BLK; r++) {
        float h  = tanhf(acc[r]);
        float sg = 1.0f / (1.0f + __expf(-h));
        out[(size_t)(r0 + r) * OUT_DIM + o] = sg;
    }
}

extern "C" void kernel_launch(void* const* d_in, const int* in_sizes, int n_in,
                              void* d_out, int out_size) {
    const float* x        = (const float*)d_in[0];   // [2048, 4096] f32
    const float* weights  = (const float*)d_in[1];   // [16384] f32
    const int*   edge_src = (const int*)d_in[2];     // [16384] i32
    const int*   edge_dst = (const int*)d_in[3];     // [16384] i32 (sorted)
    float*       out      = (float*)d_out;           // [2048, 1024] f32

    const int n_edges = in_sizes[1];

    // Opt in to >48KB dynamic smem (idempotent; not a stream op, capture-safe).
    static bool attr_set = false;
    if (!attr_set) {
        cudaFuncSetAttribute(sparse_node_main_kernel,
                             cudaFuncAttributeMaxDynamicSharedMemorySize,
                             ROWS_PER_BLK * IN_DIM * (int)sizeof(float));
        attr_set = true;
    }

    // 1) CSR offsets from sorted edge_dst
    build_offsets_kernel<<<(OUT_DIM + 1 + 127) / 128, 128>>>(edge_dst, n_edges);

    // 2) Main fused gather/segment-sum/activation kernel
    const int grid = BATCH / ROWS_PER_BLK;  // 256
    const size_t smem = (size_t)ROWS_PER_BLK * IN_DIM * sizeof(float);  // 128 KB
    sparse_node_main_kernel<<<grid, THREADS, smem>>>(x, weights, edge_src, out);
}